// round 3
// baseline (speedup 1.0000x reference)
#include <cuda_runtime.h>

#define B_   16
#define T_   512
#define C_   8
#define S_   64
#define KSZ_ 32
#define TOUT 481
#define EPSF 1e-8f

// Scratch (allocation-free rule: __device__ globals)
__device__ float g_xt[B_ * C_ * T_];     // x normalized, transposed: [b][ch][t]
__device__ float g_kn[S_ * KSZ_ * C_];   // normalized kernel [s][k][c]
__device__ float g_q2[S_ * KSZ_];        // sum_c kn^2 per (s,k)

// ---- packed f32x2 helpers (sm_100a) ---------------------------------------
__device__ __forceinline__ unsigned long long pk2(float lo, float hi) {
    unsigned long long r;
    asm("mov.b64 %0, {%1, %2};" : "=l"(r) : "f"(lo), "f"(hi));
    return r;
}
__device__ __forceinline__ unsigned long long fma2(unsigned long long a,
                                                   unsigned long long b,
                                                   unsigned long long c) {
    unsigned long long d;
    asm("fma.rn.f32x2 %0, %1, %2, %3;" : "=l"(d) : "l"(a), "l"(b), "l"(c));
    return d;
}
__device__ __forceinline__ unsigned long long mul2(unsigned long long a,
                                                   unsigned long long b) {
    unsigned long long d;
    asm("mul.rn.f32x2 %0, %1, %2;" : "=l"(d) : "l"(a), "l"(b));
    return d;
}
__device__ __forceinline__ void unpk2(unsigned long long v, float& lo, float& hi) {
    asm("mov.b64 {%0, %1}, %2;" : "=f"(lo), "=f"(hi) : "l"(v));
}

// ---------------------------------------------------------------------------
// Prep: blocks [0,128) normalize x per (b,ch) over T and transpose;
//       blocks [128,192) normalize kernel per s over (KSZ*C) and compute q2.
// ---------------------------------------------------------------------------
__global__ __launch_bounds__(256) void lsd_prep(const float* __restrict__ x,
                                                const float* __restrict__ kern) {
    const int bid = blockIdx.x;
    const int tid = threadIdx.x;
    __shared__ float red0[256];
    __shared__ float red1[256];
    __shared__ float kns[256];

    if (bid < B_ * C_) {
        const int b = bid >> 3, ch = bid & 7;
        const float v0 = x[(b * T_ + tid) * C_ + ch];
        const float v1 = x[(b * T_ + tid + 256) * C_ + ch];
        red0[tid] = v0 + v1;
        red1[tid] = v0 * v0 + v1 * v1;
        __syncthreads();
        #pragma unroll
        for (int off = 128; off > 0; off >>= 1) {
            if (tid < off) { red0[tid] += red0[tid + off]; red1[tid] += red1[tid + off]; }
            __syncthreads();
        }
        const float mean = red0[0] * (1.0f / T_);
        const float var  = red1[0] * (1.0f / T_) - mean * mean;
        const float inv  = 1.0f / (sqrtf(fmaxf(var, 0.0f)) + EPSF);
        float* xr = &g_xt[(b * C_ + ch) * T_];
        xr[tid]       = (v0 - mean) * inv;
        xr[tid + 256] = (v1 - mean) * inv;
    } else {
        const int s = bid - B_ * C_;
        const float v = kern[s * 256 + tid];
        red0[tid] = v;
        red1[tid] = v * v;
        __syncthreads();
        #pragma unroll
        for (int off = 128; off > 0; off >>= 1) {
            if (tid < off) { red0[tid] += red0[tid + off]; red1[tid] += red1[tid + off]; }
            __syncthreads();
        }
        const float mean = red0[0] * (1.0f / 256.0f);
        const float var  = red1[0] * (1.0f / 256.0f) - mean * mean;
        const float inv  = 1.0f / (sqrtf(fmaxf(var, 0.0f)) + EPSF);
        const float kn = (v - mean) * inv;
        g_kn[s * 256 + tid] = kn;
        kns[tid] = kn;
        __syncthreads();
        if (tid < KSZ_) {
            float q2 = 0.0f;
            #pragma unroll
            for (int c = 0; c < 8; c++) {
                const float t = kns[tid * 8 + c];
                q2 = fmaf(t, t, q2);
            }
            g_q2[s * KSZ_ + tid] = q2;
        }
    }
}

// ---------------------------------------------------------------------------
// Main: block = (b, 8-t tile). 256 threads:
//   k  = tid & 31          (output channel-window index)
//   tg = (tid >> 5) & 1    (t-subgroup, 4 consecutive t each)
//   sg = tid >> 6          (S-quarter: s in [16*sg, 16*sg+16))
// Each thread: 4 t-outputs over 16 prototypes; quarters merged via smem min.
// dist = p2 - 2*dot + q2 ; min over s is p2 + min_s(q2 - 2*dot).
// ---------------------------------------------------------------------------
__global__ __launch_bounds__(256) void lsd_main(float* __restrict__ out) {
    const int tid = threadIdx.x;
    const int k   = tid & 31;
    const int tg  = (tid >> 5) & 1;
    const int sg  = tid >> 6;                 // 0..3 (warp-uniform)
    const int b   = blockIdx.y;
    const int t_base = blockIdx.x * 8 + tg * 4;
    const int ch = k >> 2;
    const int m  = k & 3;
    const int wstart = t_base + 8 * m;

    __shared__ float s_mn[3 * 64 * 4];

    // window: j in [0,4), c in [0,8) -> w[0..10]
    const float* __restrict__ xrow = &g_xt[(b * C_ + ch) * T_];
    float w[11];
    #pragma unroll
    for (int i = 0; i < 11; i++) {
        int idx = wstart + i;
        if (idx > T_ - 1) idx = T_ - 1;      // clamp (padding lanes only)
        w[i] = __ldg(&xrow[idx]);
    }

    // packed sliding pairs a[i] = (w[i], w[i+1]); dot uses a[j+2e], e=0..3
    unsigned long long a[10];
    #pragma unroll
    for (int i = 0; i < 10; i++) a[i] = pk2(w[i], w[i + 1]);

    float mn[4];
    #pragma unroll
    for (int j = 0; j < 4; j++) mn[j] = 3.4e38f;

    // base pointers for this thread's S-quarter
    const ulonglong2* __restrict__ knq = (const ulonglong2*)g_kn + (sg * 16 * 32 + k) * 2;
    const float* __restrict__ q2p = g_q2 + sg * 16 * 32 + k;

    #pragma unroll
    for (int s = 0; s < 16; s++) {
        const ulonglong2 QA = knq[s * 64];        // (q0,q1),(q2,q3)
        const ulonglong2 QB = knq[s * 64 + 1];    // (q4,q5),(q6,q7)
        const float q2 = __ldg(&q2p[s * 32]);
        #pragma unroll
        for (int j = 0; j < 4; j++) {
            unsigned long long dp = mul2(a[j], QA.x);
            dp = fma2(a[j + 2], QA.y, dp);
            dp = fma2(a[j + 4], QB.x, dp);
            dp = fma2(a[j + 6], QB.y, dp);
            float lo, hi;
            unpk2(dp, lo, hi);
            // q2 - 2*lo - 2*hi  (two FFMAs, no FADD)
            const float v = fmaf(-2.0f, lo, fmaf(-2.0f, hi, q2));
            mn[j] = fminf(mn[j], v);
        }
    }

    // merge the four S-quarters
    if (sg >= 1) {
        #pragma unroll
        for (int j = 0; j < 4; j++) s_mn[(sg - 1) * 256 + (tid & 63) * 4 + j] = mn[j];
    }
    __syncthreads();
    if (sg == 0) {
        // p2[j] = sum_c w[j+c]^2 (computed late to keep regs low in hot loop)
        #pragma unroll
        for (int j = 0; j < 4; j++) {
            unsigned long long acc = mul2(a[j], a[j]);
            acc = fma2(a[j + 2], a[j + 2], acc);
            acc = fma2(a[j + 4], a[j + 4], acc);
            acc = fma2(a[j + 6], a[j + 6], acc);
            float lo, hi;
            unpk2(acc, lo, hi);
            const float p2 = lo + hi;

            const int t = t_base + j;
            if (t < TOUT) {
                float v = mn[j];
                v = fminf(v, s_mn[0 * 256 + tid * 4 + j]);
                v = fminf(v, s_mn[1 * 256 + tid * 4 + j]);
                v = fminf(v, s_mn[2 * 256 + tid * 4 + j]);
                out[(b * TOUT + t) * KSZ_ + k] = p2 + v;
            }
        }
    }
}

extern "C" void kernel_launch(void* const* d_in, const int* in_sizes, int n_in,
                              void* d_out, int out_size) {
    const float* x    = (const float*)d_in[0];   // (16, 512, 8) f32
    const float* kern = (const float*)d_in[1];   // (64, 32, 8) f32
    float* out = (float*)d_out;                  // (16, 481, 32) f32

    lsd_prep<<<B_ * C_ + S_, 256>>>(x, kern);
    dim3 grid(61, B_);                           // 61 t-tiles of 8, per batch
    lsd_main<<<grid, 256>>>(out);
}

// round 4
// speedup vs baseline: 1.0491x; 1.0491x over previous
#include <cuda_runtime.h>

#define B_   16
#define T_   512
#define C_   8
#define S_   64
#define KSZ_ 32
#define TOUT 481
#define EPSF 1e-8f

// Scratch (allocation-free rule: __device__ globals). g_xt padded +64 so the
// 3x float4 window loads at the t-edge stay in-bounds (values masked at store).
__device__ float g_xt[B_ * C_ * T_ + 64];  // x normalized, transposed: [b][ch][t]
__device__ float g_kn[S_ * KSZ_ * C_];     // normalized kernel [s][k][c]
__device__ float g_q2[S_ * KSZ_];          // sum_c kn^2 per (s,k)

// ---- packed f32x2 helpers (sm_100a) ---------------------------------------
__device__ __forceinline__ unsigned long long pk2(float lo, float hi) {
    unsigned long long r;
    asm("mov.b64 %0, {%1, %2};" : "=l"(r) : "f"(lo), "f"(hi));
    return r;
}
__device__ __forceinline__ unsigned long long fma2(unsigned long long a,
                                                   unsigned long long b,
                                                   unsigned long long c) {
    unsigned long long d;
    asm("fma.rn.f32x2 %0, %1, %2, %3;" : "=l"(d) : "l"(a), "l"(b), "l"(c));
    return d;
}
__device__ __forceinline__ unsigned long long mul2(unsigned long long a,
                                                   unsigned long long b) {
    unsigned long long d;
    asm("mul.rn.f32x2 %0, %1, %2;" : "=l"(d) : "l"(a), "l"(b));
    return d;
}
__device__ __forceinline__ void unpk2(unsigned long long v, float& lo, float& hi) {
    asm("mov.b64 {%0, %1}, %2;" : "=f"(lo), "=f"(hi) : "l"(v));
}

// ---------------------------------------------------------------------------
// Prep: blocks [0,128) normalize x per (b,ch) over T and transpose;
//       blocks [128,192) normalize kernel per s over (KSZ*C) and compute q2.
// ---------------------------------------------------------------------------
__global__ __launch_bounds__(256) void lsd_prep(const float* __restrict__ x,
                                                const float* __restrict__ kern) {
    const int bid = blockIdx.x;
    const int tid = threadIdx.x;
    __shared__ float red0[256];
    __shared__ float red1[256];
    __shared__ float kns[256];

    if (bid < B_ * C_) {
        const int b = bid >> 3, ch = bid & 7;
        const float v0 = x[(b * T_ + tid) * C_ + ch];
        const float v1 = x[(b * T_ + tid + 256) * C_ + ch];
        red0[tid] = v0 + v1;
        red1[tid] = v0 * v0 + v1 * v1;
        __syncthreads();
        #pragma unroll
        for (int off = 128; off > 0; off >>= 1) {
            if (tid < off) { red0[tid] += red0[tid + off]; red1[tid] += red1[tid + off]; }
            __syncthreads();
        }
        const float mean = red0[0] * (1.0f / T_);
        const float var  = red1[0] * (1.0f / T_) - mean * mean;
        const float inv  = 1.0f / (sqrtf(fmaxf(var, 0.0f)) + EPSF);
        float* xr = &g_xt[(b * C_ + ch) * T_];
        xr[tid]       = (v0 - mean) * inv;
        xr[tid + 256] = (v1 - mean) * inv;
    } else {
        const int s = bid - B_ * C_;
        const float v = kern[s * 256 + tid];
        red0[tid] = v;
        red1[tid] = v * v;
        __syncthreads();
        #pragma unroll
        for (int off = 128; off > 0; off >>= 1) {
            if (tid < off) { red0[tid] += red0[tid + off]; red1[tid] += red1[tid + off]; }
            __syncthreads();
        }
        const float mean = red0[0] * (1.0f / 256.0f);
        const float var  = red1[0] * (1.0f / 256.0f) - mean * mean;
        const float inv  = 1.0f / (sqrtf(fmaxf(var, 0.0f)) + EPSF);
        const float kn = (v - mean) * inv;
        g_kn[s * 256 + tid] = kn;
        kns[tid] = kn;
        __syncthreads();
        if (tid < KSZ_) {
            float q2 = 0.0f;
            #pragma unroll
            for (int c = 0; c < 8; c++) {
                const float t = kns[tid * 8 + c];
                q2 = fmaf(t, t, q2);
            }
            g_q2[s * KSZ_ + tid] = q2;
        }
    }
}

// ---------------------------------------------------------------------------
// Main: k is WARP-UNIFORM; t spreads across lanes. q-loads are warp-broadcast
// (1 wavefront) instead of 32 distinct addresses.
//   grid = (64, 16):  blockIdx.y = b, blockIdx.x = tb*16 + kpair
//   block = 256 thr = 8 warps: warp w -> kk = w>>2 (k = kpair*2+kk), sg = w&3
//   lane l handles t = tb*128 + l*4 + j, j in [0,4), over s-quarter sg (16 s).
// Quarters merged via smem min. dist = p2 + min_s(q2 - 2*dot).
// ---------------------------------------------------------------------------
__global__ __launch_bounds__(256) void lsd_main(float* __restrict__ out) {
    const int tid = threadIdx.x;
    const int l   = tid & 31;
    const int w   = tid >> 5;
    const int kk  = w >> 2;                   // 0..1 (warp-uniform)
    const int sg  = w & 3;                    // 0..3 (warp-uniform)
    const int b   = blockIdx.y;
    const int tb  = blockIdx.x >> 4;          // 0..3
    const int kp  = blockIdx.x & 15;          // 0..15
    const int k   = kp * 2 + kk;              // warp-uniform
    const int ch  = k >> 2;
    const int m   = k & 3;

    const int t0     = tb * 128 + l * 4;
    const int wstart = t0 + 8 * m;            // multiple of 4 -> 16B aligned

    __shared__ float s_mn[3 * 256];

    // window: 12 floats via 3 aligned float4 loads (w[11] unused)
    const float4* __restrict__ xv =
        (const float4*)(g_xt + (b * C_ + ch) * T_ + wstart);
    const float4 A = xv[0], Bv = xv[1], Cv = xv[2];
    float wv[11];
    wv[0] = A.x;  wv[1] = A.y;  wv[2] = A.z;  wv[3] = A.w;
    wv[4] = Bv.x; wv[5] = Bv.y; wv[6] = Bv.z; wv[7] = Bv.w;
    wv[8] = Cv.x; wv[9] = Cv.y; wv[10] = Cv.z;

    // packed sliding pairs a[i] = (w[i], w[i+1]); dot uses a[j+2e], e=0..3
    unsigned long long a[10];
    #pragma unroll
    for (int i = 0; i < 10; i++) a[i] = pk2(wv[i], wv[i + 1]);

    float mn[4];
    #pragma unroll
    for (int j = 0; j < 4; j++) mn[j] = 3.4e38f;

    // base pointers for this warp's S-quarter; warp-uniform addresses
    const ulonglong2* __restrict__ knq = (const ulonglong2*)g_kn + (sg * 512 + k) * 2;
    const float* __restrict__ q2p = g_q2 + sg * 512 + k;

    #pragma unroll
    for (int s = 0; s < 16; s++) {
        const ulonglong2 QA = knq[s * 64];        // (q0,q1),(q2,q3)
        const ulonglong2 QB = knq[s * 64 + 1];    // (q4,q5),(q6,q7)
        const float q2 = __ldg(&q2p[s * 32]);
        #pragma unroll
        for (int j = 0; j < 4; j++) {
            unsigned long long dp = mul2(a[j], QA.x);
            dp = fma2(a[j + 2], QA.y, dp);
            dp = fma2(a[j + 4], QB.x, dp);
            dp = fma2(a[j + 6], QB.y, dp);
            float lo, hi;
            unpk2(dp, lo, hi);
            const float v = fmaf(-2.0f, lo, fmaf(-2.0f, hi, q2));
            mn[j] = fminf(mn[j], v);
        }
    }

    // merge the four S-quarters (index within block: kk*128 + l*4 + j)
    if (sg >= 1) {
        #pragma unroll
        for (int j = 0; j < 4; j++)
            s_mn[(sg - 1) * 256 + kk * 128 + l * 4 + j] = mn[j];
    }
    __syncthreads();
    if (sg == 0) {
        #pragma unroll
        for (int j = 0; j < 4; j++) {
            // p2[j] = sum_c w[j+c]^2 (late, keeps hot-loop regs low)
            unsigned long long acc = mul2(a[j], a[j]);
            acc = fma2(a[j + 2], a[j + 2], acc);
            acc = fma2(a[j + 4], a[j + 4], acc);
            acc = fma2(a[j + 6], a[j + 6], acc);
            float lo, hi;
            unpk2(acc, lo, hi);
            const float p2 = lo + hi;

            const int t = t0 + j;
            if (t < TOUT) {
                const int base = kk * 128 + l * 4 + j;
                float v = mn[j];
                v = fminf(v, s_mn[0 * 256 + base]);
                v = fminf(v, s_mn[1 * 256 + base]);
                v = fminf(v, s_mn[2 * 256 + base]);
                out[(b * TOUT + t) * KSZ_ + k] = p2 + v;
            }
        }
    }
}

extern "C" void kernel_launch(void* const* d_in, const int* in_sizes, int n_in,
                              void* d_out, int out_size) {
    const float* x    = (const float*)d_in[0];   // (16, 512, 8) f32
    const float* kern = (const float*)d_in[1];   // (64, 32, 8) f32
    float* out = (float*)d_out;                  // (16, 481, 32) f32

    lsd_prep<<<B_ * C_ + S_, 256>>>(x, kern);
    dim3 grid(64, B_);                           // (tb, kpair) x b
    lsd_main<<<grid, 256>>>(out);
}